// round 10
// baseline (speedup 1.0000x reference)
#include <cuda_runtime.h>
#include <cuda_bf16.h>
#include <cstdint>

// VectorQuantizer forward — round 10: 2-way-split bf16 mma.sync (m16n8k16,
// baseline PTX) + exact fp32 scalar rescore of near-tie rows.
//   z [262144 x 64] f32, emb [512 x 64] f32
//   out: [z_q 16777216][loss 1][indices-as-float 262144]
//
// dot(z,e) ~= HMMA over concat K=192: A=[z1|z1|z2], B=[e1|e2|e1] (exact
// 2-term bf16 splits; error <= ~1.4e-6 << fp32 dist quantum 7.6e-6@64).
// dist = (||z||^2 - 2*dot) + ||e||^2 fp32, argmin. Rows whose top-2 MMA
// dists are closer than EPS are rescored over all 512 codes with the exact
// scalar chain of R4-R6 (which matched the reference bit-for-bit), so the
// final indices equal the scalar kernel's on every row.
//
// 148 persistent CTAs x 512 threads; emb splits (2 x 512 x 144B) built once
// in smem (147KB). Tile = 256 rows; warp w owns rows w*16..w*16+15.

#define NUM_EMB   512
#define EMB_DIM   64
#define M_TILE    256
#define BN        (64 * 4096)
#define NTILES    (BN / M_TILE)            // 1024
#define ZQ_ELEMS  (BN * EMB_DIM)
#define NCTA      148
#define NTHREADS  512
#define B_PITCH   144                      // bytes per code row (72 bf16)
#define B_SPLIT_STRIDE (NUM_EMB * B_PITCH) // 73728
#define DYN_SMEM  (2 * B_SPLIT_STRIDE)     // 147456
#define EPS_TIE   6.0e-5f                  // ~4 dist quanta @ ||z||^2 <= 128

__device__ double       g_partials[NCTA];
__device__ unsigned int g_count;

__device__ __forceinline__ uint32_t pack_bf2(__nv_bfloat16 lo, __nv_bfloat16 hi) {
    __nv_bfloat162 t(lo, hi);
    return *reinterpret_cast<uint32_t*>(&t);
}

struct Split2 { __nv_bfloat16 a, b; };
__device__ __forceinline__ Split2 split2(float x) {
    Split2 s;
    s.a = __float2bfloat16_rn(x);
    s.b = __float2bfloat16_rn(x - __bfloat162float(s.a));   // exact residual
    return s;
}

__device__ __forceinline__ void mma_bf16(float* d, const uint32_t* a,
                                         const uint32_t* b) {
    asm volatile(
        "mma.sync.aligned.m16n8k16.row.col.f32.bf16.bf16.f32 "
        "{%0,%1,%2,%3}, {%4,%5,%6,%7}, {%8,%9}, {%0,%1,%2,%3};"
        : "+f"(d[0]), "+f"(d[1]), "+f"(d[2]), "+f"(d[3])
        : "r"(a[0]), "r"(a[1]), "r"(a[2]), "r"(a[3]), "r"(b[0]), "r"(b[1]));
}

// top-2 update (values only for 'second')
__device__ __forceinline__ void top2(float d, int c, float& b, int& bi, float& s) {
    if (d < b)      { s = b; b = d; bi = c; }
    else if (d < s) { s = d; }
}

__global__ __launch_bounds__(NTHREADS, 1)
void vq_mma(const float* __restrict__ z, const float* __restrict__ emb,
            float* __restrict__ out, float* __restrict__ idx_out,
            int write_loss)
{
    extern __shared__ char bsm[];            // 2 emb splits, 144B-pitch rows
    __shared__ float  enorm_s[NUM_EMB];
    __shared__ float  znorm_s[M_TILE];
    __shared__ float  best_v_s[M_TILE];
    __shared__ int    best_i_s[M_TILE];
    __shared__ int    tie_list[M_TILE];
    __shared__ int    nflag_s;
    __shared__ double dsum_s[NTHREADS];
    __shared__ unsigned int is_last_s;

    const int tid  = threadIdx.x;
    const int lane = tid & 31;
    const int warp = tid >> 5;               // 0..15
    const int m    = lane & 3;                // quad column selector (k pairs)
    const int ng   = lane >> 2;               // n-index within 8-block / row grp

    // ---- one-time: emb -> 2 bf16 splits + exact ||e||^2 (R4-R6 chain) ----
    {
        const int c = tid;                    // 512 threads = 512 codes
        const float4* er = reinterpret_cast<const float4*>(emb + (size_t)c * EMB_DIM);
        char* r0 = bsm + (size_t)c * B_PITCH;
        float s = 0.f;
        #pragma unroll 4
        for (int q = 0; q < 16; q++) {
            float4 v = er[q];
            float x4[4] = {v.x, v.y, v.z, v.w};
            #pragma unroll
            for (int e = 0; e < 4; e++) {
                float x = x4[e];
                s = fmaf(x, x, s);            // sequential d-order (matches R4-6)
                Split2 sp = split2(x);
                int off = (q * 4 + e) * 2;
                *reinterpret_cast<__nv_bfloat16*>(r0 + off)                  = sp.a;
                *reinterpret_cast<__nv_bfloat16*>(r0 + B_SPLIT_STRIDE + off) = sp.b;
            }
        }
        enorm_s[c] = s;
    }
    __syncthreads();

    double lsum = 0.0;

    for (int tile = blockIdx.x; tile < NTILES; tile += NCTA) {
        const size_t row0 = (size_t)tile * M_TILE;
        if (tid == 0) nflag_s = 0;

        // ---- znorm: 1 thread/row, sequential fmaf (R4-R6 rounding) ----
        if (tid < M_TILE) {
            const float4* zr = reinterpret_cast<const float4*>(
                z + (row0 + (size_t)tid) * EMB_DIM);
            float s = 0.f;
            #pragma unroll 4
            for (int q = 0; q < 16; q++) {
                float4 v = zr[q];
                s = fmaf(v.x, v.x, s); s = fmaf(v.y, v.y, s);
                s = fmaf(v.z, v.z, s); s = fmaf(v.w, v.w, s);
            }
            znorm_s[tid] = s;
        }

        // ---- A fragments: rows (r, r+8), 2 splits x 4 k16-chunks ----
        const size_t gr0 = row0 + (size_t)warp * 16 + ng;
        const float* z0 = z + gr0 * EMB_DIM;
        const float* z1 = z + (gr0 + 8) * EMB_DIM;

        uint32_t A[2][4][4];
        #pragma unroll
        for (int c = 0; c < 4; c++) {
            #pragma unroll
            for (int h = 0; h < 2; h++) {
                int k0 = c * 16 + m * 2 + h * 8;
                float2 v0 = *reinterpret_cast<const float2*>(z0 + k0);
                float2 v1 = *reinterpret_cast<const float2*>(z1 + k0);
                Split2 x0 = split2(v0.x), x1 = split2(v0.y);
                Split2 y0 = split2(v1.x), y1 = split2(v1.y);
                A[0][c][h * 2 + 0] = pack_bf2(x0.a, x1.a);
                A[0][c][h * 2 + 1] = pack_bf2(y0.a, y1.a);
                A[1][c][h * 2 + 0] = pack_bf2(x0.b, x1.b);
                A[1][c][h * 2 + 1] = pack_bf2(y0.b, y1.b);
            }
        }
        __syncthreads();                      // znorm + nflag ready

        const float zn0 = znorm_s[warp * 16 + ng];
        const float zn1 = znorm_s[warp * 16 + ng + 8];

        float b0 = 3.402823466e38f, s0 = 3.402823466e38f;
        float b1 = 3.402823466e38f, s1 = 3.402823466e38f;
        int   i0 = 0x7fffffff, i1 = 0x7fffffff;

        // ---- n-loop: 64 blocks of 8 codes, K=192 concat (e1,e2,e1) ----
        for (int nb = 0; nb < 64; nb++) {
            const int ncol = nb * 8 + ng;
            const char* bp = bsm + (size_t)ncol * B_PITCH + (size_t)(m * 2) * 2;

            uint32_t B1[4][2], B2[4][2];      // split-1 / split-2 B frags
            #pragma unroll
            for (int c = 0; c < 4; c++)
                #pragma unroll
                for (int h = 0; h < 2; h++) {
                    B1[c][h] = *reinterpret_cast<const uint32_t*>(
                        bp + (c * 16 + h * 8) * 2);
                    B2[c][h] = *reinterpret_cast<const uint32_t*>(
                        bp + B_SPLIT_STRIDE + (c * 16 + h * 8) * 2);
                }

            float acc[4] = {0.f, 0.f, 0.f, 0.f};
            #pragma unroll
            for (int c = 0; c < 4; c++) mma_bf16(acc, A[0][c], B1[c]); // z1e1
            #pragma unroll
            for (int c = 0; c < 4; c++) mma_bf16(acc, A[0][c], B2[c]); // z1e2
            #pragma unroll
            for (int c = 0; c < 4; c++) mma_bf16(acc, A[1][c], B1[c]); // z2e1

            const int c0 = nb * 8 + m * 2;
            float2 en = *reinterpret_cast<const float2*>(enorm_s + c0);
            float d00 = __fadd_rn(__fsub_rn(zn0, __fmul_rn(2.0f, acc[0])), en.x);
            float d01 = __fadd_rn(__fsub_rn(zn0, __fmul_rn(2.0f, acc[1])), en.y);
            float d10 = __fadd_rn(__fsub_rn(zn1, __fmul_rn(2.0f, acc[2])), en.x);
            float d11 = __fadd_rn(__fsub_rn(zn1, __fmul_rn(2.0f, acc[3])), en.y);
            top2(d00, c0,     b0, i0, s0);
            top2(d01, c0 + 1, b0, i0, s0);
            top2(d10, c0,     b1, i1, s1);
            top2(d11, c0 + 1, b1, i1, s1);
        }

        // ---- quad top-2 merge (lanes 4*ng..4*ng+3), lower-idx tie-break ----
        #pragma unroll
        for (int off = 1; off <= 2; off <<= 1) {
            float ob0 = __shfl_xor_sync(0xffffffffu, b0, off);
            int   oi0 = __shfl_xor_sync(0xffffffffu, i0, off);
            float os0 = __shfl_xor_sync(0xffffffffu, s0, off);
            float ob1 = __shfl_xor_sync(0xffffffffu, b1, off);
            int   oi1 = __shfl_xor_sync(0xffffffffu, i1, off);
            float os1 = __shfl_xor_sync(0xffffffffu, s1, off);
            if (ob0 < b0 || (ob0 == b0 && oi0 < i0)) {
                s0 = fminf(b0, os0); b0 = ob0; i0 = oi0;
            } else s0 = fminf(ob0, s0);
            if (ob1 < b1 || (ob1 == b1 && oi1 < i1)) {
                s1 = fminf(b1, os1); b1 = ob1; i1 = oi1;
            } else s1 = fminf(ob1, s1);
        }
        if (m == 0) {
            const int lr = warp * 16 + ng;
            best_v_s[lr] = b0;  best_i_s[lr] = i0;
            best_v_s[lr + 8] = b1;  best_i_s[lr + 8] = i1;
            if (s0 - b0 < EPS_TIE) tie_list[atomicAdd(&nflag_s, 1)] = lr;
            if (s1 - b1 < EPS_TIE) tie_list[atomicAdd(&nflag_s, 1)] = lr + 8;
        }
        __syncthreads();

        // ---- rescore near-tie rows with exact R4-R6 scalar chain ----
        {
            const int nf = nflag_s;
            for (int f = warp; f < nf; f += 16) {
                const int row = tie_list[f];
                const float zn = znorm_s[row];
                const float4* zr = reinterpret_cast<const float4*>(
                    z + (row0 + (size_t)row) * EMB_DIM);
                float bv = 3.402823466e38f;
                int   bi = 0x7fffffff;
                for (int j = 0; j < 16; j++) {
                    const int code = lane + 32 * j;       // ascending in j
                    const float4* er = reinterpret_cast<const float4*>(
                        emb + (size_t)code * EMB_DIM);
                    float dot = 0.f;
                    #pragma unroll 4
                    for (int q = 0; q < 16; q++) {
                        float4 zv = zr[q], ev = er[q];
                        dot = fmaf(zv.x, ev.x, dot);
                        dot = fmaf(zv.y, ev.y, dot);
                        dot = fmaf(zv.z, ev.z, dot);
                        dot = fmaf(zv.w, ev.w, dot);
                    }
                    float dist = __fadd_rn(__fsub_rn(zn, __fmul_rn(2.0f, dot)),
                                           enorm_s[code]);
                    if (dist < bv) { bv = dist; bi = code; }
                }
                #pragma unroll
                for (int off = 16; off; off >>= 1) {
                    float ov = __shfl_xor_sync(0xffffffffu, bv, off);
                    int   oi = __shfl_xor_sync(0xffffffffu, bi, off);
                    if (ov < bv || (ov == bv && oi < bi)) { bv = ov; bi = oi; }
                }
                if (lane == 0) { best_v_s[row] = bv; best_i_s[row] = bi; }
            }
        }
        __syncthreads();

        // ---- indices + loss ----
        if (tid < M_TILE) {
            if (idx_out) idx_out[row0 + tid] = (float)best_i_s[tid];
            lsum += (double)best_v_s[tid];    // min dist = ||z - z_q||^2
        }

        // ---- z_q = z + (e - z): 2 threads/row, 8 float4 each ----
        {
            const int r = tid >> 1, q = tid & 1;
            const int bi = best_i_s[r];
            const float4* zr = reinterpret_cast<const float4*>(
                z + (row0 + (size_t)r) * EMB_DIM) + q * 8;
            const float4* er = reinterpret_cast<const float4*>(
                emb + (size_t)bi * EMB_DIM) + q * 8;
            float4* o = reinterpret_cast<float4*>(
                out + (row0 + (size_t)r) * EMB_DIM) + q * 8;
            #pragma unroll
            for (int i = 0; i < 8; i++) {
                float4 zv = zr[i], ev = er[i], w;
                w.x = __fadd_rn(zv.x, __fsub_rn(ev.x, zv.x));
                w.y = __fadd_rn(zv.y, __fsub_rn(ev.y, zv.y));
                w.z = __fadd_rn(zv.z, __fsub_rn(ev.z, zv.z));
                w.w = __fadd_rn(zv.w, __fsub_rn(ev.w, zv.w));
                o[i] = w;
            }
        }
        __syncthreads();                      // smem reuse next tile
    }

    // ---- loss finalization ----
    dsum_s[tid] = lsum;
    __syncthreads();
    if (!write_loss) return;
    #pragma unroll
    for (int k = NTHREADS / 2; k; k >>= 1) {
        if (tid < k) dsum_s[tid] += dsum_s[tid + k];
        __syncthreads();
    }
    if (tid == 0) {
        g_partials[blockIdx.x] = dsum_s[0];
        __threadfence();
        is_last_s = (atomicAdd(&g_count, 1u) == gridDim.x - 1);
    }
    __syncthreads();
    if (!is_last_s) return;

    double s = 0.0;
    for (int i = tid; i < (int)gridDim.x; i += NTHREADS) s += g_partials[i];
    dsum_s[tid] = s;
    __syncthreads();
    #pragma unroll
    for (int k = NTHREADS / 2; k; k >>= 1) {
        if (tid < k) dsum_s[tid] += dsum_s[tid + k];
        __syncthreads();
    }
    if (tid == 0) {
        out[ZQ_ELEMS] = (float)(1.25 * dsum_s[0] /
                                (double)((double)BN * (double)EMB_DIM));
        g_count = 0;                          // reset for graph replay
    }
}

extern "C" void kernel_launch(void* const* d_in, const int* in_sizes, int n_in,
                              void* d_out, int out_size)
{
    const float* z   = (const float*)d_in[0];
    const float* emb = (const float*)d_in[1];
    float* out = (float*)d_out;

    cudaFuncSetAttribute(vq_mma, cudaFuncAttributeMaxDynamicSharedMemorySize,
                         DYN_SMEM);

    // out layout: [z_q (16777216)] [loss (1)] [indices (262144)]
    const bool extras = (out_size >= ZQ_ELEMS + 1 + BN);
    float* idx_out = extras ? (out + ZQ_ELEMS + 1) : nullptr;
    const int write_loss = (out_size > ZQ_ELEMS) ? 1 : 0;

    vq_mma<<<NCTA, NTHREADS, DYN_SMEM>>>(z, emb, out, idx_out, write_loss);
}